// round 1
// baseline (speedup 1.0000x reference)
#include <cuda_runtime.h>
#include <math.h>
#include <stdint.h>

#define NP  2048
#define B_  8
#define KNN 20

// ------------------- device scratch (allocation-free) -------------------
__device__ float d_xx[B_*NP];
__device__ float d_D[(size_t)B_*NP*NP];                       // 134 MB distances
__device__ int   d_idx[B_*NP*KNN];
__device__ __align__(16) float d_xT[(size_t)B_*NP*128];       // [B,N,C] gather layout
__device__ __align__(16) float d_cat[(size_t)B_*512*NP];      // x1..x4 stacked [B,512,N]
__device__ float d_mx[(size_t)B_*NP*256];                     // pre-BN max over k
__device__ __align__(16) float d_Y[(size_t)B_*1024*NP];       // final conv out
__device__ float d_sum[1024];
__device__ float d_sq[1024];
__device__ float d_scale[1024];
__device__ float d_shift[1024];

__device__ __forceinline__ const float* layer_src(const float* ext, int coff, int b, int bstride) {
    if (ext) return ext + (size_t)b * bstride;
    return d_cat + (size_t)b * 512 * NP + (size_t)coff * NP;
}

// ---- transpose src slice [C,NP] -> d_xT [NP,C] ----
__global__ void k_transpose(const float* ext, int coff, int bstride, int C) {
    int b = blockIdx.z;
    const float* S = layer_src(ext, coff, b, bstride);
    __shared__ float tile[32][33];
    int n0 = blockIdx.x*32, c0 = blockIdx.y*32;
    #pragma unroll
    for (int q=0;q<4;q++) {
        int c = c0 + threadIdx.y + q*8;
        if (c < C) tile[threadIdx.y + q*8][threadIdx.x] = S[(size_t)c*NP + n0 + threadIdx.x];
    }
    __syncthreads();
    #pragma unroll
    for (int q=0;q<4;q++) {
        int n = n0 + threadIdx.y + q*8;
        int c = c0 + threadIdx.x;
        if (c < C) d_xT[((size_t)b*NP + n)*C + c] = tile[threadIdx.x][threadIdx.y + q*8];
    }
}

// ---- squared norms per point ----
__global__ void k_norms(const float* ext, int coff, int bstride, int C) {
    int b = blockIdx.y;
    int n = blockIdx.x*256 + threadIdx.x;
    const float* S = layer_src(ext, coff, b, bstride);
    float s = 0.f;
    for (int c=0;c<C;c++){ float v = S[(size_t)c*NP + n]; s += v*v; }
    d_xx[b*NP + n] = s;
}

// ---- gram / negative sq-dist matrix: D = 2*x^T x - xx_n - xx_m ----
__global__ void k_gram(const float* ext, int coff, int bstride, int C) {
    int b = blockIdx.z;
    const float* S = layer_src(ext, coff, b, bstride);
    int n0 = blockIdx.y*64, m0 = blockIdx.x*64;
    __shared__ __align__(16) float As[16][64];
    __shared__ __align__(16) float Bs[16][64];
    int tid = threadIdx.x;
    int tx = tid & 15, ty = tid >> 4;
    int lr = tid >> 4;         // 0..15 (k row)
    int lc = (tid & 15) * 4;   // col within 64
    float acc[4][4] = {};
    for (int c0=0;c0<C;c0+=16) {
        float4 av, bv;
        if (c0 + lr < C) {
            av = *(const float4*)&S[(size_t)(c0+lr)*NP + n0 + lc];
            bv = *(const float4*)&S[(size_t)(c0+lr)*NP + m0 + lc];
        } else { av = make_float4(0.f,0.f,0.f,0.f); bv = av; }
        *(float4*)&As[lr][lc] = av;
        *(float4*)&Bs[lr][lc] = bv;
        __syncthreads();
        #pragma unroll
        for (int kk=0;kk<16;kk++) {
            float4 a  = *(float4*)&As[kk][ty*4];
            float4 bq = *(float4*)&Bs[kk][tx*4];
            float ar[4] = {a.x,a.y,a.z,a.w};
            float br[4] = {bq.x,bq.y,bq.z,bq.w};
            #pragma unroll
            for (int i=0;i<4;i++)
              #pragma unroll
              for (int j=0;j<4;j++)
                acc[i][j] += ar[i]*br[j];
        }
        __syncthreads();
    }
    float xn[4], xm[4];
    #pragma unroll
    for (int i=0;i<4;i++) xn[i] = d_xx[b*NP + n0 + ty*4 + i];
    #pragma unroll
    for (int j=0;j<4;j++) xm[j] = d_xx[b*NP + m0 + tx*4 + j];
    #pragma unroll
    for (int i=0;i<4;i++)
      #pragma unroll
      for (int j=0;j<4;j++)
        d_D[((size_t)b*NP + n0+ty*4+i)*NP + m0+tx*4+j] = 2.f*acc[i][j] - xn[i] - xm[j];
}

// ---- top-20 per row: 20 rounds of packed-u64 argmax (ties -> smallest index) ----
__global__ void k_topk() {
    int bn = blockIdx.x;
    __shared__ unsigned long long keys[NP];
    __shared__ unsigned long long wred[8];
    const float* row = d_D + (size_t)bn*NP;
    int tid = threadIdx.x;
    for (int m=tid; m<NP; m+=256) {
        unsigned int fb = __float_as_uint(row[m]);
        unsigned int u = (fb & 0x80000000u) ? ~fb : (fb | 0x80000000u);
        keys[m] = ((unsigned long long)u << 32) | (unsigned int)(NP-1-m);
    }
    __syncthreads();
    for (int r=0;r<KNN;r++) {
        unsigned long long best = 0ull;
        #pragma unroll
        for (int q=0;q<8;q++) {
            unsigned long long k = keys[tid + q*256];
            if (k > best) best = k;
        }
        #pragma unroll
        for (int off=16;off;off>>=1) {
            unsigned long long o = __shfl_down_sync(0xffffffffu, best, off);
            if (o > best) best = o;
        }
        if ((tid & 31) == 0) wred[tid >> 5] = best;
        __syncthreads();
        if (tid == 0) {
            unsigned long long bb = wred[0];
            #pragma unroll
            for (int i=1;i<8;i++) if (wred[i] > bb) bb = wred[i];
            int m = (NP-1) - (int)(bb & 0xffffffffull);
            d_idx[bn*KNN + r] = m;
            keys[m] = 0ull;
        }
        __syncthreads();
    }
}

__global__ void k_zero() {
    int i = blockIdx.x*blockDim.x + threadIdx.x;
    if (i < 1024) { d_sum[i]=0.f; d_sq[i]=0.f; }
}

// ---- edge conv: gather 20 nbrs, y = W[:, :C]*nbr + t, track max_k + channel stats ----
template<int C, int O>
__global__ void k_edgeconv(const float* __restrict__ W) {
    int bn = blockIdx.x;
    int b = bn >> 11;
    int n = bn & (NP-1);
    constexpr int CP = (C < 4) ? 4 : C;
    __shared__ __align__(16) float s_ctr[CP];
    __shared__ __align__(16) float s_nbr[KNN*CP];
    __shared__ int s_idx[KNN];
    int tid = threadIdx.x;
    int TH = blockDim.x;
    if (tid < KNN) s_idx[tid] = d_idx[bn*KNN + tid];
    const float* xb = d_xT + (size_t)b*NP*C;
    for (int c=tid;c<C;c+=TH) s_ctr[c] = xb[(size_t)n*C + c];
    __syncthreads();
    for (int e=tid;e<KNN*C;e+=TH) {
        int j = e / C, c = e - j*C;
        s_nbr[j*CP + c] = xb[(size_t)s_idx[j]*C + c];
    }
    __syncthreads();
    for (int o=tid;o<O;o+=TH) {
        const float* Wo = W + o*2*C;
        float t = 0.f;
        #pragma unroll 4
        for (int c=0;c<C;c++) t += (Wo[C+c] - Wo[c]) * s_ctr[c];
        float y[KNN];
        #pragma unroll
        for (int k=0;k<KNN;k++) y[k] = t;
        if constexpr ((C & 3) == 0) {
            for (int c=0;c<C;c+=4) {
                float4 w = *(const float4*)&Wo[c];
                #pragma unroll
                for (int k=0;k<KNN;k++) {
                    float4 v = *(const float4*)&s_nbr[k*CP + c];
                    y[k] += w.x*v.x + w.y*v.y + w.z*v.z + w.w*v.w;
                }
            }
        } else {
            for (int c=0;c<C;c++) {
                float w = Wo[c];
                #pragma unroll
                for (int k=0;k<KNN;k++) y[k] += w * s_nbr[k*CP + c];
            }
        }
        float mx = -1e30f, s = 0.f, sq = 0.f;
        #pragma unroll
        for (int k=0;k<KNN;k++) {
            mx = fmaxf(mx, y[k]);
            s += y[k];
            sq += y[k]*y[k];
        }
        d_mx[(size_t)bn*O + o] = mx;
        atomicAdd(&d_sum[o], s);
        atomicAdd(&d_sq[o], sq);
    }
}

// ---- BN stats -> affine scale/shift per channel ----
__global__ void k_finalize(const float* __restrict__ g, const float* __restrict__ bb,
                           float inv, int O) {
    int o = blockIdx.x*blockDim.x + threadIdx.x;
    if (o >= O) return;
    float mean = d_sum[o]*inv;
    float var  = d_sq[o]*inv - mean*mean;
    float sc = g[o] / sqrtf(var + 1e-5f);
    d_scale[o] = sc;
    d_shift[o] = bb[o] - mean*sc;
}

// ---- apply BN+leaky to max_k and transpose into d_cat slice [B, coff+O, N] ----
__global__ void k_apply(int O, int coff) {
    int b = blockIdx.z;
    int n0 = blockIdx.x*32, o0 = blockIdx.y*32;
    __shared__ float tile[32][33];
    #pragma unroll
    for (int q=0;q<4;q++) {
        int n = n0 + threadIdx.y + q*8;
        int o = o0 + threadIdx.x;
        float v = d_mx[((size_t)b*NP + n)*O + o];
        float z = v*d_scale[o] + d_shift[o];
        z = (z > 0.f) ? z : 0.2f*z;
        tile[threadIdx.x][threadIdx.y + q*8] = z;
    }
    __syncthreads();
    #pragma unroll
    for (int q=0;q<4;q++) {
        int o = o0 + threadIdx.y + q*8;
        int n = n0 + threadIdx.x;
        d_cat[((size_t)b*512 + coff + o)*NP + n] = tile[threadIdx.y + q*8][threadIdx.x];
    }
}

// ---- final 512->1024 conv: Y[b,o,n] = sum_c cat[b,c,n]*W5[o,c], with channel stats ----
__global__ void k_fgemm(const float* __restrict__ W5) {
    int b = blockIdx.z;
    int o0 = blockIdx.y*64, n0 = blockIdx.x*64;
    __shared__ __align__(16) float As[16][64];
    __shared__ __align__(16) float Bs[16][64];
    const float* catb = d_cat + (size_t)b*512*NP;
    int tid = threadIdx.x;
    int tx = tid & 15, ty = tid >> 4;
    int a_oi = tid >> 2;
    int a_k4 = (tid & 3) * 4;
    int b_kk = tid >> 4;
    int b_n4 = (tid & 15) * 4;
    float acc[4][4] = {};
    for (int c0=0;c0<512;c0+=16) {
        float4 w = *(const float4*)&W5[(size_t)(o0 + a_oi)*512 + c0 + a_k4];
        As[a_k4+0][a_oi]=w.x; As[a_k4+1][a_oi]=w.y; As[a_k4+2][a_oi]=w.z; As[a_k4+3][a_oi]=w.w;
        *(float4*)&Bs[b_kk][b_n4] = *(const float4*)&catb[(size_t)(c0 + b_kk)*NP + n0 + b_n4];
        __syncthreads();
        #pragma unroll
        for (int kk=0;kk<16;kk++) {
            float4 a  = *(float4*)&As[kk][ty*4];
            float4 bq = *(float4*)&Bs[kk][tx*4];
            float ar[4]={a.x,a.y,a.z,a.w}, br[4]={bq.x,bq.y,bq.z,bq.w};
            #pragma unroll
            for (int i=0;i<4;i++)
              #pragma unroll
              for (int j=0;j<4;j++)
                acc[i][j] += ar[i]*br[j];
        }
        __syncthreads();
    }
    float s[4]={0.f,0.f,0.f,0.f}, sq[4]={0.f,0.f,0.f,0.f};
    #pragma unroll
    for (int i=0;i<4;i++) {
        int o = o0 + ty*4 + i;
        #pragma unroll
        for (int j=0;j<4;j++) {
            float v = acc[i][j];
            d_Y[((size_t)b*1024 + o)*NP + n0 + tx*4 + j] = v;
            s[i] += v; sq[i] += v*v;
        }
    }
    #pragma unroll
    for (int i=0;i<4;i++) {
        #pragma unroll
        for (int off=8;off;off>>=1) {
            s[i]  += __shfl_down_sync(0xffffffffu, s[i],  off, 16);
            sq[i] += __shfl_down_sync(0xffffffffu, sq[i], off, 16);
        }
    }
    if (tx == 0) {
        #pragma unroll
        for (int i=0;i<4;i++) {
            atomicAdd(&d_sum[o0+ty*4+i], s[i]);
            atomicAdd(&d_sq [o0+ty*4+i], sq[i]);
        }
    }
}

// ---- per (b,o): BN+leaky then max and mean over n ----
__global__ void k_freduce(float* __restrict__ out) {
    int bo = blockIdx.x;
    int b = bo >> 10, o = bo & 1023;
    const float* y = d_Y + (size_t)bo*NP;
    float sc = d_scale[o], sh = d_shift[o];
    int tid = threadIdx.x;
    float mx = -1e30f, s = 0.f;
    #pragma unroll
    for (int q=0;q<8;q++) {
        float z = y[tid + q*256]*sc + sh;
        z = (z > 0.f) ? z : 0.2f*z;
        mx = fmaxf(mx, z); s += z;
    }
    #pragma unroll
    for (int off=16;off;off>>=1) {
        mx = fmaxf(mx, __shfl_down_sync(0xffffffffu, mx, off));
        s += __shfl_down_sync(0xffffffffu, s, off);
    }
    __shared__ float smx[8], ssm[8];
    if ((tid&31)==0) { smx[tid>>5]=mx; ssm[tid>>5]=s; }
    __syncthreads();
    if (tid==0) {
        #pragma unroll
        for (int i=1;i<8;i++){ mx=fmaxf(mx,smx[i]); s+=ssm[i]; }
        out[(size_t)b*2048 + o] = mx;
        out[(size_t)b*2048 + 1024 + o] = s * (1.f/2048.f);
    }
}

// ------------------------------- host -------------------------------
static void run_edge(const float* ext, int coff_in, int bstride, int C, int O,
                     const float* W, const float* g, const float* bb, int coff_out) {
    dim3 tb(32,8);
    k_transpose<<<dim3(NP/32, (C+31)/32, B_), tb>>>(ext, coff_in, bstride, C);
    k_norms<<<dim3(NP/256, B_), 256>>>(ext, coff_in, bstride, C);
    k_gram<<<dim3(NP/64, NP/64, B_), 256>>>(ext, coff_in, bstride, C);
    k_topk<<<B_*NP, 256>>>();
    k_zero<<<4,256>>>();
    int th = (O < 128) ? O : 128;
    if      (C==3   && O==64 ) k_edgeconv<3,64  ><<<B_*NP, th>>>(W);
    else if (C==64  && O==64 ) k_edgeconv<64,64 ><<<B_*NP, th>>>(W);
    else if (C==64  && O==128) k_edgeconv<64,128><<<B_*NP, th>>>(W);
    else if (C==128 && O==256) k_edgeconv<128,256><<<B_*NP, th>>>(W);
    k_finalize<<<(O+127)/128,128>>>(g, bb, 1.f/(float)(B_*NP*KNN), O);
    k_apply<<<dim3(NP/32, O/32, B_), tb>>>(O, coff_out);
}

extern "C" void kernel_launch(void* const* d_in, const int* in_sizes, int n_in,
                              void* d_out, int out_size) {
    (void)in_sizes; (void)n_in; (void)out_size;
    const float* x  = (const float*)d_in[0];
    const float* W1 = (const float*)d_in[1];
    const float* W2 = (const float*)d_in[2];
    const float* W3 = (const float*)d_in[3];
    const float* W4 = (const float*)d_in[4];
    const float* W5 = (const float*)d_in[5];
    const float* g1 = (const float*)d_in[6];  const float* b1 = (const float*)d_in[7];
    const float* g2 = (const float*)d_in[8];  const float* b2 = (const float*)d_in[9];
    const float* g3 = (const float*)d_in[10]; const float* b3 = (const float*)d_in[11];
    const float* g4 = (const float*)d_in[12]; const float* b4 = (const float*)d_in[13];
    const float* g5 = (const float*)d_in[14]; const float* b5 = (const float*)d_in[15];
    float* out = (float*)d_out;

    run_edge(x,       0,   3*NP,   3,  64, W1, g1, b1,   0);
    run_edge(nullptr, 0,   0,     64,  64, W2, g2, b2,  64);
    run_edge(nullptr, 64,  0,     64, 128, W3, g3, b3, 128);
    run_edge(nullptr, 128, 0,    128, 256, W4, g4, b4, 256);

    k_zero<<<4,256>>>();
    k_fgemm<<<dim3(NP/64, 1024/64, B_), 256>>>(W5);
    k_finalize<<<8,128>>>(g5, b5, 1.f/(float)(B_*NP), 1024);
    k_freduce<<<B_*1024, 256>>>(out);
}

// round 2
// speedup vs baseline: 1.9426x; 1.9426x over previous
#include <cuda_runtime.h>
#include <math.h>
#include <stdint.h>

#define NP  2048
#define B_  8
#define KNN 20

// ------------------- device scratch (allocation-free) -------------------
__device__ float d_xx[B_*NP];
__device__ float d_D[(size_t)B_*NP*NP];                       // 134 MB distances
__device__ int   d_idx[B_*NP*KNN];
__device__ __align__(16) float d_xT[(size_t)B_*NP*128];       // [B,N,C] gather layout
__device__ __align__(16) float d_cat[(size_t)B_*512*NP];      // x1..x4 stacked [B,512,N]
__device__ __align__(16) float d_mx[(size_t)B_*NP*256];       // pre-BN max over k
__device__ __align__(16) float d_T[(size_t)B_*NP*256];        // t-term per (bn,o)
__device__ __align__(16) float d_Wd[256*128];                 // W2 - W1 halves
__device__ __align__(16) float d_Y[(size_t)B_*1024*NP];       // final conv out
__device__ float d_sum[1024];
__device__ float d_sq[1024];
__device__ float d_scale[1024];
__device__ float d_shift[1024];

__device__ __forceinline__ const float* layer_src(const float* ext, int coff, int b, int bstride) {
    if (ext) return ext + (size_t)b * bstride;
    return d_cat + (size_t)b * 512 * NP + (size_t)coff * NP;
}

// ---- transpose src slice [C,NP] -> d_xT [NP,C] ----
__global__ void k_transpose(const float* ext, int coff, int bstride, int C) {
    int b = blockIdx.z;
    const float* S = layer_src(ext, coff, b, bstride);
    __shared__ float tile[32][33];
    int n0 = blockIdx.x*32, c0 = blockIdx.y*32;
    #pragma unroll
    for (int q=0;q<4;q++) {
        int c = c0 + threadIdx.y + q*8;
        if (c < C) tile[threadIdx.y + q*8][threadIdx.x] = S[(size_t)c*NP + n0 + threadIdx.x];
    }
    __syncthreads();
    #pragma unroll
    for (int q=0;q<4;q++) {
        int n = n0 + threadIdx.y + q*8;
        int c = c0 + threadIdx.x;
        if (c < C) d_xT[((size_t)b*NP + n)*C + c] = tile[threadIdx.x][threadIdx.y + q*8];
    }
}

// ---- squared norms per point ----
__global__ void k_norms(const float* ext, int coff, int bstride, int C) {
    int b = blockIdx.y;
    int n = blockIdx.x*256 + threadIdx.x;
    const float* S = layer_src(ext, coff, b, bstride);
    float s = 0.f;
    for (int c=0;c<C;c++){ float v = S[(size_t)c*NP + n]; s += v*v; }
    d_xx[b*NP + n] = s;
}

// ---- gram / negative sq-dist matrix: D = 2*x^T x - xx_n - xx_m ----
__global__ void k_gram(const float* ext, int coff, int bstride, int C) {
    int b = blockIdx.z;
    const float* S = layer_src(ext, coff, b, bstride);
    int n0 = blockIdx.y*64, m0 = blockIdx.x*64;
    __shared__ __align__(16) float As[16][64];
    __shared__ __align__(16) float Bs[16][64];
    int tid = threadIdx.x;
    int tx = tid & 15, ty = tid >> 4;
    int lr = tid >> 4;
    int lc = (tid & 15) * 4;
    float acc[4][4] = {};
    for (int c0=0;c0<C;c0+=16) {
        float4 av, bv;
        if (c0 + lr < C) {
            av = *(const float4*)&S[(size_t)(c0+lr)*NP + n0 + lc];
            bv = *(const float4*)&S[(size_t)(c0+lr)*NP + m0 + lc];
        } else { av = make_float4(0.f,0.f,0.f,0.f); bv = av; }
        *(float4*)&As[lr][lc] = av;
        *(float4*)&Bs[lr][lc] = bv;
        __syncthreads();
        #pragma unroll
        for (int kk=0;kk<16;kk++) {
            float4 a  = *(float4*)&As[kk][ty*4];
            float4 bq = *(float4*)&Bs[kk][tx*4];
            float ar[4] = {a.x,a.y,a.z,a.w};
            float br[4] = {bq.x,bq.y,bq.z,bq.w};
            #pragma unroll
            for (int i=0;i<4;i++)
              #pragma unroll
              for (int j=0;j<4;j++)
                acc[i][j] += ar[i]*br[j];
        }
        __syncthreads();
    }
    float xn[4], xm[4];
    #pragma unroll
    for (int i=0;i<4;i++) xn[i] = d_xx[b*NP + n0 + ty*4 + i];
    #pragma unroll
    for (int j=0;j<4;j++) xm[j] = d_xx[b*NP + m0 + tx*4 + j];
    #pragma unroll
    for (int i=0;i<4;i++)
      #pragma unroll
      for (int j=0;j<4;j++)
        d_D[((size_t)b*NP + n0+ty*4+i)*NP + m0+tx*4+j] = 2.f*acc[i][j] - xn[i] - xm[j];
}

// ---- top-20 SET per row via 8-bit radix histogram select (order-free) ----
__global__ void k_select() {
    int bn = blockIdx.x;
    __shared__ unsigned int key[NP];      // orderable u32 keys
    __shared__ unsigned int hist[256];
    __shared__ unsigned int sh_v, sh_need2, sh_cnt;
    const float* row = d_D + (size_t)bn*NP;
    int tid = threadIdx.x;  // 256
    #pragma unroll
    for (int q=0;q<8;q++) {
        int m = tid + q*256;
        unsigned int fb = __float_as_uint(row[m]);
        key[m] = (fb & 0x80000000u) ? ~fb : (fb | 0x80000000u);
    }
    unsigned prefix = 0, pmask = 0, need = KNN, needEq = 0;
    int done = 0;
    for (int shift = 24; shift >= 0; shift -= 8) {
        hist[tid] = 0;
        __syncthreads();
        #pragma unroll
        for (int q=0;q<8;q++) {
            unsigned k = key[tid + q*256];
            if ((k & pmask) == prefix) atomicAdd(&hist[(k >> shift) & 255u], 1u);
        }
        __syncthreads();
        if (tid < 32) {
            unsigned base = tid*8;
            unsigned suf[8]; unsigned s = 0;
            #pragma unroll
            for (int j=7;j>=0;j--){ s += hist[base+j]; suf[j] = s; }
            unsigned incl = s;
            #pragma unroll
            for (int d=1; d<32; d<<=1) {
                unsigned o = __shfl_down_sync(0xffffffffu, incl, d);
                if (tid + d < 32) incl += o;
            }
            unsigned lane_above = incl - s;
            #pragma unroll
            for (int j=0;j<8;j++) {
                unsigned cg  = lane_above + suf[j];
                unsigned cgt = cg - hist[base+j];
                if (cgt < need && need <= cg) { sh_v = base + j; sh_need2 = need - cgt; }
            }
        }
        __syncthreads();
        unsigned v = sh_v, n2 = sh_need2, binc = hist[v];
        prefix |= v << shift;
        pmask  |= 0xffu << shift;
        need = n2;
        if (n2 == binc) { done = 1; break; }
        needEq = n2;
        __syncthreads();   // protect hist before re-zero next level
    }
    if (tid == 0) sh_cnt = 0;
    __syncthreads();
    #pragma unroll
    for (int q=0;q<8;q++) {
        int m = tid + q*256;
        unsigned k = key[m];
        bool take = done ? (k >= prefix) : (k > prefix);
        if (take) { unsigned slot = atomicAdd(&sh_cnt, 1u); d_idx[bn*KNN + slot] = m; }
    }
    __syncthreads();
    if (!done) {
        (void)needEq;
        #pragma unroll
        for (int q=0;q<8;q++) {
            int m = tid + q*256;
            if (key[m] == prefix) {
                unsigned slot = atomicAdd(&sh_cnt, 1u);
                if (slot < KNN) d_idx[bn*KNN + slot] = m;
            }
        }
    }
}

__global__ void k_zero() {
    int i = blockIdx.x*blockDim.x + threadIdx.x;
    if (i < 1024) { d_sum[i]=0.f; d_sq[i]=0.f; }
}

// ---- legacy edge conv for layer 1 (C=3 — tiny) ----
template<int C, int O>
__global__ void k_edgeconv(const float* __restrict__ W) {
    int bn = blockIdx.x;
    int b = bn >> 11;
    int n = bn & (NP-1);
    constexpr int CP = (C < 4) ? 4 : C;
    __shared__ __align__(16) float s_ctr[CP];
    __shared__ __align__(16) float s_nbr[KNN*CP];
    __shared__ int s_idx[KNN];
    int tid = threadIdx.x;
    int TH = blockDim.x;
    if (tid < KNN) s_idx[tid] = d_idx[bn*KNN + tid];
    const float* xb = d_xT + (size_t)b*NP*C;
    for (int c=tid;c<C;c+=TH) s_ctr[c] = xb[(size_t)n*C + c];
    __syncthreads();
    for (int e=tid;e<KNN*C;e+=TH) {
        int j = e / C, c = e - j*C;
        s_nbr[j*CP + c] = xb[(size_t)s_idx[j]*C + c];
    }
    __syncthreads();
    for (int o=tid;o<O;o+=TH) {
        const float* Wo = W + o*2*C;
        float t = 0.f;
        for (int c=0;c<C;c++) t += (Wo[C+c] - Wo[c]) * s_ctr[c];
        float y[KNN];
        #pragma unroll
        for (int k=0;k<KNN;k++) y[k] = t;
        for (int c=0;c<C;c++) {
            float w = Wo[c];
            #pragma unroll
            for (int k=0;k<KNN;k++) y[k] += w * s_nbr[k*CP + c];
        }
        float mx = -1e30f, s = 0.f, sq = 0.f;
        #pragma unroll
        for (int k=0;k<KNN;k++) {
            mx = fmaxf(mx, y[k]);
            s += y[k];
            sq += y[k]*y[k];
        }
        d_mx[(size_t)bn*O + o] = mx;
        atomicAdd(&d_sum[o], s);
        atomicAdd(&d_sq[o], sq);
    }
}

// ---- Wd = W[:,C:] - W[:,:C] ----
__global__ void k_wd(const float* __restrict__ W, int O, int C) {
    int i = blockIdx.x*256 + threadIdx.x;
    if (i < O*C) {
        int o = i / C, c = i - o*C;
        d_Wd[i] = W[(size_t)o*2*C + C + c] - W[(size_t)o*2*C + c];
    }
}

// ---- t-term GEMM: d_T[bn][o] = sum_c Wd[o][c] * src[c][n] ----
template<int C, int O>
__global__ void k_tconv(const float* ext, int coff, int bstride) {
    int b = blockIdx.z;
    int o0 = blockIdx.y*64, n0 = blockIdx.x*64;
    __shared__ __align__(16) float As[16][64];
    __shared__ __align__(16) float Bs[16][64];
    const float* src = layer_src(ext, coff, b, bstride);
    int tid = threadIdx.x;
    int tx = tid & 15, ty = tid >> 4;
    int a_oi = tid >> 2;
    int a_k4 = (tid & 3) * 4;
    int b_kk = tid >> 4;
    int b_n4 = (tid & 15) * 4;
    float acc[4][4] = {};
    for (int c0=0;c0<C;c0+=16) {
        float4 w = *(const float4*)&d_Wd[(size_t)(o0 + a_oi)*C + c0 + a_k4];
        As[a_k4+0][a_oi]=w.x; As[a_k4+1][a_oi]=w.y; As[a_k4+2][a_oi]=w.z; As[a_k4+3][a_oi]=w.w;
        *(float4*)&Bs[b_kk][b_n4] = *(const float4*)&src[(size_t)(c0 + b_kk)*NP + n0 + b_n4];
        __syncthreads();
        #pragma unroll
        for (int kk=0;kk<16;kk++) {
            float4 a  = *(float4*)&As[kk][ty*4];
            float4 bq = *(float4*)&Bs[kk][tx*4];
            float ar[4]={a.x,a.y,a.z,a.w}, br[4]={bq.x,bq.y,bq.z,bq.w};
            #pragma unroll
            for (int i=0;i<4;i++)
              #pragma unroll
              for (int j=0;j<4;j++)
                acc[i][j] += ar[i]*br[j];
        }
        __syncthreads();
    }
    #pragma unroll
    for (int j=0;j<4;j++) {
        float4 tv = make_float4(acc[0][j],acc[1][j],acc[2][j],acc[3][j]);
        *(float4*)&d_T[((size_t)b*NP + n0 + tx*4 + j)*O + o0 + ty*4] = tv;
    }
}

// ---- edge conv core: a_k = Wn·nbr_k from smem, stats over k, combine with t ----
// threads = KS * (OC/4) * P = 256
template<int C, int O, int OC, int P, int KS>
__global__ void k_edgecore(const float* __restrict__ W) {
    constexpr int OG = OC/4;
    extern __shared__ float sm[];
    float*  s_wf  = sm;                             // [OG][(C+1)] float4 groups
    float*  s_nbr = sm + (size_t)OG*(C+1)*4;        // [P][KNN][C]
    int*    s_idx = (int*)(s_nbr + (size_t)P*KNN*C);

    int tid = threadIdx.x;
    int bn0 = blockIdx.x * P;
    int b   = bn0 >> 11;
    int o0  = blockIdx.y * OC;

    if (tid < P*KNN) s_idx[tid] = d_idx[(bn0 + tid/KNN)*KNN + tid%KNN];
    __syncthreads();

    // stage Wn (first half of W) into banked float4 groups
    for (int e = tid; e < OC*C; e += 256) {
        int o = e / C, c = e - o*C;
        s_wf[(size_t)(o>>2)*(C+1)*4 + c*4 + (o&3)] = W[(size_t)(o0 + o)*(2*C) + c];
    }
    // gather neighbor features
    const float* xb = d_xT + (size_t)b*NP*C;
    for (int e = tid; e < P*KNN*C; e += 256) {
        int p = e / (KNN*C);
        int r = e - p*(KNN*C);
        int j = r / C, c = r - j*C;
        s_nbr[e] = xb[(size_t)s_idx[p*KNN + j]*C + c];
    }
    __syncthreads();

    const int ks = tid % KS;
    const int og = (tid / KS) % OG;
    const int p  = tid / (KS * OG);
    const float4* wq = (const float4*)sm + (size_t)og*(C+1);
    const float* nb0 = s_nbr + (size_t)p*KNN*C;

    float m0=-3.4e38f, m1=-3.4e38f, m2=-3.4e38f, m3=-3.4e38f;
    float s0=0.f,s1=0.f,s2=0.f,s3=0.f;
    float q0=0.f,q1=0.f,q2=0.f,q3=0.f;
    for (int k = ks; k < KNN; k += KS) {
        const float* nb = nb0 + k*C;
        float y0=0.f,y1=0.f,y2=0.f,y3=0.f;
        #pragma unroll 8
        for (int c=0;c<C;c++) {
            float4 w = wq[c];
            float v = nb[c];
            y0 = fmaf(w.x, v, y0); y1 = fmaf(w.y, v, y1);
            y2 = fmaf(w.z, v, y2); y3 = fmaf(w.w, v, y3);
        }
        m0=fmaxf(m0,y0); m1=fmaxf(m1,y1); m2=fmaxf(m2,y2); m3=fmaxf(m3,y3);
        s0+=y0; s1+=y1; s2+=y2; s3+=y3;
        q0=fmaf(y0,y0,q0); q1=fmaf(y1,y1,q1); q2=fmaf(y2,y2,q2); q3=fmaf(y3,y3,q3);
    }
    #pragma unroll
    for (int d=1; d<KS; d<<=1) {
        m0=fmaxf(m0,__shfl_xor_sync(0xffffffffu,m0,d));
        m1=fmaxf(m1,__shfl_xor_sync(0xffffffffu,m1,d));
        m2=fmaxf(m2,__shfl_xor_sync(0xffffffffu,m2,d));
        m3=fmaxf(m3,__shfl_xor_sync(0xffffffffu,m3,d));
        s0+=__shfl_xor_sync(0xffffffffu,s0,d);
        s1+=__shfl_xor_sync(0xffffffffu,s1,d);
        s2+=__shfl_xor_sync(0xffffffffu,s2,d);
        s3+=__shfl_xor_sync(0xffffffffu,s3,d);
        q0+=__shfl_xor_sync(0xffffffffu,q0,d);
        q1+=__shfl_xor_sync(0xffffffffu,q1,d);
        q2+=__shfl_xor_sync(0xffffffffu,q2,d);
        q3+=__shfl_xor_sync(0xffffffffu,q3,d);
    }
    if (ks == 0) {
        int bn = bn0 + p;
        int o4 = og*4;
        float4 t4 = *(const float4*)&d_T[(size_t)bn*O + o0 + o4];
        float4 mx = make_float4(m0+t4.x, m1+t4.y, m2+t4.z, m3+t4.w);
        *(float4*)&d_mx[(size_t)bn*O + o0 + o4] = mx;
        float tt[4] = {t4.x,t4.y,t4.z,t4.w};
        float ss[4] = {s0,s1,s2,s3};
        float qq[4] = {q0,q1,q2,q3};
        #pragma unroll
        for (int i=0;i<4;i++) {
            atomicAdd(&d_sum[o0+o4+i], ss[i] + 20.f*tt[i]);
            atomicAdd(&d_sq [o0+o4+i], qq[i] + 2.f*tt[i]*ss[i] + 20.f*tt[i]*tt[i]);
        }
    }
}

// ---- BN stats -> affine scale/shift per channel ----
__global__ void k_finalize(const float* __restrict__ g, const float* __restrict__ bb,
                           float inv, int O) {
    int o = blockIdx.x*blockDim.x + threadIdx.x;
    if (o >= O) return;
    float mean = d_sum[o]*inv;
    float var  = d_sq[o]*inv - mean*mean;
    float sc = g[o] / sqrtf(var + 1e-5f);
    d_scale[o] = sc;
    d_shift[o] = bb[o] - mean*sc;
}

// ---- apply BN+leaky to max_k and transpose into d_cat slice ----
__global__ void k_apply(int O, int coff) {
    int b = blockIdx.z;
    int n0 = blockIdx.x*32, o0 = blockIdx.y*32;
    __shared__ float tile[32][33];
    #pragma unroll
    for (int q=0;q<4;q++) {
        int n = n0 + threadIdx.y + q*8;
        int o = o0 + threadIdx.x;
        float v = d_mx[((size_t)b*NP + n)*O + o];
        float z = v*d_scale[o] + d_shift[o];
        z = (z > 0.f) ? z : 0.2f*z;
        tile[threadIdx.x][threadIdx.y + q*8] = z;
    }
    __syncthreads();
    #pragma unroll
    for (int q=0;q<4;q++) {
        int o = o0 + threadIdx.y + q*8;
        int n = n0 + threadIdx.x;
        d_cat[((size_t)b*512 + coff + o)*NP + n] = tile[threadIdx.y + q*8][threadIdx.x];
    }
}

// ---- final 512->1024 conv with channel stats ----
__global__ void k_fgemm(const float* __restrict__ W5) {
    int b = blockIdx.z;
    int o0 = blockIdx.y*64, n0 = blockIdx.x*64;
    __shared__ __align__(16) float As[16][64];
    __shared__ __align__(16) float Bs[16][64];
    const float* catb = d_cat + (size_t)b*512*NP;
    int tid = threadIdx.x;
    int tx = tid & 15, ty = tid >> 4;
    int a_oi = tid >> 2;
    int a_k4 = (tid & 3) * 4;
    int b_kk = tid >> 4;
    int b_n4 = (tid & 15) * 4;
    float acc[4][4] = {};
    for (int c0=0;c0<512;c0+=16) {
        float4 w = *(const float4*)&W5[(size_t)(o0 + a_oi)*512 + c0 + a_k4];
        As[a_k4+0][a_oi]=w.x; As[a_k4+1][a_oi]=w.y; As[a_k4+2][a_oi]=w.z; As[a_k4+3][a_oi]=w.w;
        *(float4*)&Bs[b_kk][b_n4] = *(const float4*)&catb[(size_t)(c0 + b_kk)*NP + n0 + b_n4];
        __syncthreads();
        #pragma unroll
        for (int kk=0;kk<16;kk++) {
            float4 a  = *(float4*)&As[kk][ty*4];
            float4 bq = *(float4*)&Bs[kk][tx*4];
            float ar[4]={a.x,a.y,a.z,a.w}, br[4]={bq.x,bq.y,bq.z,bq.w};
            #pragma unroll
            for (int i=0;i<4;i++)
              #pragma unroll
              for (int j=0;j<4;j++)
                acc[i][j] += ar[i]*br[j];
        }
        __syncthreads();
    }
    float s[4]={0.f,0.f,0.f,0.f}, sq[4]={0.f,0.f,0.f,0.f};
    #pragma unroll
    for (int i=0;i<4;i++) {
        int o = o0 + ty*4 + i;
        #pragma unroll
        for (int j=0;j<4;j++) {
            float v = acc[i][j];
            d_Y[((size_t)b*1024 + o)*NP + n0 + tx*4 + j] = v;
            s[i] += v; sq[i] += v*v;
        }
    }
    #pragma unroll
    for (int i=0;i<4;i++) {
        #pragma unroll
        for (int off=8;off;off>>=1) {
            s[i]  += __shfl_down_sync(0xffffffffu, s[i],  off, 16);
            sq[i] += __shfl_down_sync(0xffffffffu, sq[i], off, 16);
        }
    }
    if (tx == 0) {
        #pragma unroll
        for (int i=0;i<4;i++) {
            atomicAdd(&d_sum[o0+ty*4+i], s[i]);
            atomicAdd(&d_sq [o0+ty*4+i], sq[i]);
        }
    }
}

// ---- per (b,o): BN+leaky then max and mean over n ----
__global__ void k_freduce(float* __restrict__ out) {
    int bo = blockIdx.x;
    int b = bo >> 10, o = bo & 1023;
    const float* y = d_Y + (size_t)bo*NP;
    float sc = d_scale[o], sh = d_shift[o];
    int tid = threadIdx.x;
    float mx = -1e30f, s = 0.f;
    #pragma unroll
    for (int q=0;q<8;q++) {
        float z = y[tid + q*256]*sc + sh;
        z = (z > 0.f) ? z : 0.2f*z;
        mx = fmaxf(mx, z); s += z;
    }
    #pragma unroll
    for (int off=16;off;off>>=1) {
        mx = fmaxf(mx, __shfl_down_sync(0xffffffffu, mx, off));
        s += __shfl_down_sync(0xffffffffu, s, off);
    }
    __shared__ float smx[8], ssm[8];
    if ((tid&31)==0) { smx[tid>>5]=mx; ssm[tid>>5]=s; }
    __syncthreads();
    if (tid==0) {
        #pragma unroll
        for (int i=1;i<8;i++){ mx=fmaxf(mx,smx[i]); s+=ssm[i]; }
        out[(size_t)b*2048 + o] = mx;
        out[(size_t)b*2048 + 1024 + o] = s * (1.f/2048.f);
    }
}

// ------------------------------- host -------------------------------
template<int C, int O, int OC, int P, int KS>
static void run_edge2(const float* ext, int coff_in, int bstride,
                      const float* W, const float* g, const float* bb, int coff_out) {
    dim3 tb(32,8);
    k_transpose<<<dim3(NP/32, (C+31)/32, B_), tb>>>(ext, coff_in, bstride, C);
    k_norms<<<dim3(NP/256, B_), 256>>>(ext, coff_in, bstride, C);
    k_gram<<<dim3(NP/64, NP/64, B_), 256>>>(ext, coff_in, bstride, C);
    k_select<<<B_*NP, 256>>>();
    k_zero<<<4,256>>>();
    k_wd<<<(O*C + 255)/256, 256>>>(W, O, C);
    k_tconv<C,O><<<dim3(NP/64, O/64, B_), 256>>>(ext, coff_in, bstride);
    constexpr int SM_BYTES = ((OC/4)*(C+1)*4 + P*KNN*C)*4 + P*KNN*4 + 16;
    cudaFuncSetAttribute(reinterpret_cast<const void*>(k_edgecore<C,O,OC,P,KS>),
                         cudaFuncAttributeMaxDynamicSharedMemorySize, SM_BYTES);
    k_edgecore<C,O,OC,P,KS><<<dim3(B_*NP/P, O/OC), 256, SM_BYTES>>>(W);
    k_finalize<<<(O+127)/128,128>>>(g, bb, 1.f/(float)(B_*NP*KNN), O);
    k_apply<<<dim3(NP/32, O/32, B_), tb>>>(O, coff_out);
}

extern "C" void kernel_launch(void* const* d_in, const int* in_sizes, int n_in,
                              void* d_out, int out_size) {
    (void)in_sizes; (void)n_in; (void)out_size;
    const float* x  = (const float*)d_in[0];
    const float* W1 = (const float*)d_in[1];
    const float* W2 = (const float*)d_in[2];
    const float* W3 = (const float*)d_in[3];
    const float* W4 = (const float*)d_in[4];
    const float* W5 = (const float*)d_in[5];
    const float* g1 = (const float*)d_in[6];  const float* b1 = (const float*)d_in[7];
    const float* g2 = (const float*)d_in[8];  const float* b2 = (const float*)d_in[9];
    const float* g3 = (const float*)d_in[10]; const float* b3 = (const float*)d_in[11];
    const float* g4 = (const float*)d_in[12]; const float* b4 = (const float*)d_in[13];
    const float* g5 = (const float*)d_in[14]; const float* b5 = (const float*)d_in[15];
    float* out = (float*)d_out;

    // ---- layer 1 (C=3): legacy tiny path + new select ----
    {
        dim3 tb(32,8);
        k_transpose<<<dim3(NP/32, 1, B_), tb>>>(x, 0, 3*NP, 3);
        k_norms<<<dim3(NP/256, B_), 256>>>(x, 0, 3*NP, 3);
        k_gram<<<dim3(NP/64, NP/64, B_), 256>>>(x, 0, 3*NP, 3);
        k_select<<<B_*NP, 256>>>();
        k_zero<<<4,256>>>();
        k_edgeconv<3,64><<<B_*NP, 64>>>(W1);
        k_finalize<<<1,128>>>(g1, b1, 1.f/(float)(B_*NP*KNN), 64);
        k_apply<<<dim3(NP/32, 2, B_), tb>>>(64, 0);
    }
    run_edge2<64, 64, 64, 4, 4>(nullptr, 0,   0, W2, g2, b2,  64);
    run_edge2<64, 128,128,4, 2>(nullptr, 64,  0, W3, g3, b3, 128);
    run_edge2<128,256,128,2, 4>(nullptr, 128, 0, W4, g4, b4, 256);

    k_zero<<<4,256>>>();
    k_fgemm<<<dim3(NP/64, 1024/64, B_), 256>>>(W5);
    k_finalize<<<8,128>>>(g5, b5, 1.f/(float)(B_*NP), 1024);
    k_freduce<<<B_*1024, 256>>>(out);
}

// round 4
// speedup vs baseline: 5.5058x; 2.8343x over previous
#include <cuda_runtime.h>
#include <math.h>
#include <stdint.h>

#define NP  2048
#define B_  8
#define KNN 20

// ------------------- device scratch (allocation-free) -------------------
__device__ float d_xx[B_*NP];
__device__ float d_D[(size_t)B_*NP*NP];                       // 134 MB distances
__device__ int   d_idx[B_*NP*KNN];
__device__ __align__(16) float d_xT[(size_t)B_*NP*4];         // layer-1 gather layout
__device__ __align__(16) float d_cat[(size_t)B_*512*NP];      // x1..x4 stacked [B,512,N]
__device__ __align__(16) float d_mx[(size_t)B_*NP*256];       // pre-BN max over k
__device__ __align__(16) float d_AT[(size_t)B_*NP*512];       // [bn][2O]: A then T
__device__ __align__(16) float d_WG[512*128];                 // [Wn; Wd] rows
__device__ __align__(16) float d_Y[(size_t)B_*1024*NP];       // final conv out
__device__ float d_sum[1024];
__device__ float d_sq[1024];
__device__ float d_scale[1024];
__device__ float d_shift[1024];

// ---- packed f32x2 helpers (FFMA2 path) ----
__device__ __forceinline__ unsigned long long pk2(float lo, float hi) {
    unsigned long long r;
    asm("mov.b64 %0, {%1, %2};" : "=l"(r) : "f"(lo), "f"(hi));
    return r;
}
__device__ __forceinline__ float2 upk2(unsigned long long v) {
    float lo, hi;
    asm("mov.b64 {%0, %1}, %2;" : "=f"(lo), "=f"(hi) : "l"(v));
    return make_float2(lo, hi);
}
__device__ __forceinline__ unsigned long long fma2(unsigned long long a,
                                                   unsigned long long b,
                                                   unsigned long long c) {
    unsigned long long d;
    asm("fma.rn.f32x2 %0, %1, %2, %3;" : "=l"(d) : "l"(a), "l"(b), "l"(c));
    return d;
}

__device__ __forceinline__ const float* layer_src(const float* ext, int coff, int b, int bstride) {
    if (ext) return ext + (size_t)b * bstride;
    return d_cat + (size_t)b * 512 * NP + (size_t)coff * NP;
}

// ---- transpose src slice [C,NP] -> d_xT [NP,C] (layer 1 only) ----
__global__ void k_transpose(const float* ext, int coff, int bstride, int C) {
    int b = blockIdx.z;
    const float* S = layer_src(ext, coff, b, bstride);
    __shared__ float tile[32][33];
    int n0 = blockIdx.x*32, c0 = blockIdx.y*32;
    #pragma unroll
    for (int q=0;q<4;q++) {
        int c = c0 + threadIdx.y + q*8;
        if (c < C) tile[threadIdx.y + q*8][threadIdx.x] = S[(size_t)c*NP + n0 + threadIdx.x];
    }
    __syncthreads();
    #pragma unroll
    for (int q=0;q<4;q++) {
        int n = n0 + threadIdx.y + q*8;
        int c = c0 + threadIdx.x;
        if (c < C) d_xT[((size_t)b*NP + n)*C + c] = tile[threadIdx.x][threadIdx.y + q*8];
    }
}

// ---- squared norms per point ----
__global__ void k_norms(const float* ext, int coff, int bstride, int C) {
    int b = blockIdx.y;
    int n = blockIdx.x*256 + threadIdx.x;
    const float* S = layer_src(ext, coff, b, bstride);
    float s = 0.f;
    for (int c=0;c<C;c++){ float v = S[(size_t)c*NP + n]; s += v*v; }
    d_xx[b*NP + n] = s;
}

// ---- gram / negative sq-dist matrix: D = 2*x^T x - xx_n - xx_m (FFMA2) ----
__global__ void k_gram(const float* ext, int coff, int bstride, int C) {
    int b = blockIdx.z;
    const float* S = layer_src(ext, coff, b, bstride);
    int n0 = blockIdx.y*64, m0 = blockIdx.x*64;
    __shared__ __align__(16) float As[16][64];
    __shared__ __align__(16) float Bs[16][64];
    int tid = threadIdx.x;
    int tx = tid & 15, ty = tid >> 4;
    int lr = tid >> 4;
    int lc = (tid & 15) * 4;
    unsigned long long acc2[4][2] = {};
    for (int c0=0;c0<C;c0+=16) {
        float4 av, bv;
        if (c0 + lr < C) {
            av = *(const float4*)&S[(size_t)(c0+lr)*NP + n0 + lc];
            bv = *(const float4*)&S[(size_t)(c0+lr)*NP + m0 + lc];
        } else { av = make_float4(0.f,0.f,0.f,0.f); bv = av; }
        *(float4*)&As[lr][lc] = av;
        *(float4*)&Bs[lr][lc] = bv;
        __syncthreads();
        #pragma unroll
        for (int kk=0;kk<16;kk++) {
            float4 a  = *(float4*)&As[kk][ty*4];
            float4 bq = *(float4*)&Bs[kk][tx*4];
            unsigned long long bp0 = pk2(bq.x, bq.y);
            unsigned long long bp1 = pk2(bq.z, bq.w);
            float ar[4] = {a.x,a.y,a.z,a.w};
            #pragma unroll
            for (int i=0;i<4;i++) {
                unsigned long long ad = pk2(ar[i], ar[i]);
                acc2[i][0] = fma2(ad, bp0, acc2[i][0]);
                acc2[i][1] = fma2(ad, bp1, acc2[i][1]);
            }
        }
        __syncthreads();
    }
    float xn[4], xm[4];
    #pragma unroll
    for (int i=0;i<4;i++) xn[i] = d_xx[b*NP + n0 + ty*4 + i];
    #pragma unroll
    for (int j=0;j<4;j++) xm[j] = d_xx[b*NP + m0 + tx*4 + j];
    #pragma unroll
    for (int i=0;i<4;i++) {
        float2 u0 = upk2(acc2[i][0]);
        float2 u1 = upk2(acc2[i][1]);
        float4 w;
        w.x = 2.f*u0.x - xn[i] - xm[0];
        w.y = 2.f*u0.y - xn[i] - xm[1];
        w.z = 2.f*u1.x - xn[i] - xm[2];
        w.w = 2.f*u1.y - xn[i] - xm[3];
        *(float4*)&d_D[((size_t)b*NP + n0+ty*4+i)*NP + m0+tx*4] = w;
    }
}

// ---- top-20 SET per row via 8-bit radix histogram select (order-free) ----
__global__ void k_select() {
    int bn = blockIdx.x;
    __shared__ unsigned int key[NP];
    __shared__ unsigned int hist[256];
    __shared__ unsigned int sh_v, sh_need2, sh_cnt;
    const float* row = d_D + (size_t)bn*NP;
    int tid = threadIdx.x;  // 256
    #pragma unroll
    for (int q=0;q<8;q++) {
        int m = tid + q*256;
        unsigned int fb = __float_as_uint(row[m]);
        key[m] = (fb & 0x80000000u) ? ~fb : (fb | 0x80000000u);
    }
    unsigned prefix = 0, pmask = 0, need = KNN;
    int done = 0;
    for (int shift = 24; shift >= 0; shift -= 8) {
        hist[tid] = 0;
        __syncthreads();
        #pragma unroll
        for (int q=0;q<8;q++) {
            unsigned k = key[tid + q*256];
            if ((k & pmask) == prefix) atomicAdd(&hist[(k >> shift) & 255u], 1u);
        }
        __syncthreads();
        if (tid < 32) {
            unsigned base = tid*8;
            unsigned suf[8]; unsigned s = 0;
            #pragma unroll
            for (int j=7;j>=0;j--){ s += hist[base+j]; suf[j] = s; }
            unsigned incl = s;
            #pragma unroll
            for (int d=1; d<32; d<<=1) {
                unsigned o = __shfl_down_sync(0xffffffffu, incl, d);
                if (tid + d < 32) incl += o;
            }
            unsigned lane_above = incl - s;
            #pragma unroll
            for (int j=0;j<8;j++) {
                unsigned cg  = lane_above + suf[j];
                unsigned cgt = cg - hist[base+j];
                if (cgt < need && need <= cg) { sh_v = base + j; sh_need2 = need - cgt; }
            }
        }
        __syncthreads();
        unsigned v = sh_v, n2 = sh_need2, binc = hist[v];
        prefix |= v << shift;
        pmask  |= 0xffu << shift;
        need = n2;
        if (n2 == binc) { done = 1; break; }
        __syncthreads();
    }
    if (tid == 0) sh_cnt = 0;
    __syncthreads();
    #pragma unroll
    for (int q=0;q<8;q++) {
        int m = tid + q*256;
        unsigned k = key[m];
        bool take = done ? (k >= prefix) : (k > prefix);
        if (take) { unsigned slot = atomicAdd(&sh_cnt, 1u); d_idx[bn*KNN + slot] = m; }
    }
    __syncthreads();
    if (!done) {
        #pragma unroll
        for (int q=0;q<8;q++) {
            int m = tid + q*256;
            if (key[m] == prefix) {
                unsigned slot = atomicAdd(&sh_cnt, 1u);
                if (slot < KNN) d_idx[bn*KNN + slot] = m;
            }
        }
    }
}

__global__ void k_zero() {
    int i = blockIdx.x*blockDim.x + threadIdx.x;
    if (i < 1024) { d_sum[i]=0.f; d_sq[i]=0.f; }
}

// ---- legacy edge conv for layer 1 (C=3 — tiny) ----
template<int C, int O>
__global__ void k_edgeconv(const float* __restrict__ W) {
    int bn = blockIdx.x;
    int b = bn >> 11;
    int n = bn & (NP-1);
    constexpr int CP = (C < 4) ? 4 : C;
    __shared__ __align__(16) float s_ctr[CP];
    __shared__ __align__(16) float s_nbr[KNN*CP];
    __shared__ int s_idx[KNN];
    int tid = threadIdx.x;
    int TH = blockDim.x;
    if (tid < KNN) s_idx[tid] = d_idx[bn*KNN + tid];
    const float* xb = d_xT + (size_t)b*NP*C;
    for (int c=tid;c<C;c+=TH) s_ctr[c] = xb[(size_t)n*C + c];
    __syncthreads();
    for (int e=tid;e<KNN*C;e+=TH) {
        int j = e / C, c = e - j*C;
        s_nbr[j*CP + c] = xb[(size_t)s_idx[j]*C + c];
    }
    __syncthreads();
    for (int o=tid;o<O;o+=TH) {
        const float* Wo = W + o*2*C;
        float t = 0.f;
        for (int c=0;c<C;c++) t += (Wo[C+c] - Wo[c]) * s_ctr[c];
        float y[KNN];
        #pragma unroll
        for (int k=0;k<KNN;k++) y[k] = t;
        for (int c=0;c<C;c++) {
            float w = Wo[c];
            #pragma unroll
            for (int k=0;k<KNN;k++) y[k] += w * s_nbr[k*CP + c];
        }
        float mx = -1e30f, s = 0.f, sq = 0.f;
        #pragma unroll
        for (int k=0;k<KNN;k++) {
            mx = fmaxf(mx, y[k]);
            s += y[k];
            sq += y[k]*y[k];
        }
        d_mx[(size_t)bn*O + o] = mx;
        atomicAdd(&d_sum[o], s);
        atomicAdd(&d_sq[o], sq);
    }
}

// ---- build combined weights: rows [0,O) = Wn, rows [O,2O) = W2 - Wn ----
__global__ void k_wprep(const float* __restrict__ W, int O, int C) {
    int i = blockIdx.x*256 + threadIdx.x;
    if (i >= 2*O*C) return;
    int o = i / C, c = i - o*C;
    if (o < O) d_WG[i] = W[(size_t)o*2*C + c];
    else {
        int oo = o - O;
        d_WG[i] = W[(size_t)oo*2*C + C + c] - W[(size_t)oo*2*C + c];
    }
}

// ---- AT GEMM: d_AT[bn][o] = sum_c WG[o][c] * src[c][n], o in [0,2O) (FFMA2) ----
template<int C, int TWO_O>
__global__ void k_atgemm(const float* ext, int coff, int bstride) {
    int b = blockIdx.z;
    int o0 = blockIdx.y*64, n0 = blockIdx.x*64;
    __shared__ __align__(16) float As[16][64];
    __shared__ __align__(16) float Bs[16][64];
    const float* src = layer_src(ext, coff, b, bstride);
    int tid = threadIdx.x;
    int tx = tid & 15, ty = tid >> 4;
    int a_oi = tid >> 2;
    int a_k4 = (tid & 3) * 4;
    int b_kk = tid >> 4;
    int b_n4 = (tid & 15) * 4;
    unsigned long long acc2[4][2] = {};
    for (int c0=0;c0<C;c0+=16) {
        float4 w = *(const float4*)&d_WG[(size_t)(o0 + a_oi)*C + c0 + a_k4];
        As[a_k4+0][a_oi]=w.x; As[a_k4+1][a_oi]=w.y; As[a_k4+2][a_oi]=w.z; As[a_k4+3][a_oi]=w.w;
        *(float4*)&Bs[b_kk][b_n4] = *(const float4*)&src[(size_t)(c0 + b_kk)*NP + n0 + b_n4];
        __syncthreads();
        #pragma unroll
        for (int kk=0;kk<16;kk++) {
            float4 a  = *(float4*)&As[kk][ty*4];
            float4 bq = *(float4*)&Bs[kk][tx*4];
            unsigned long long bp0 = pk2(bq.x, bq.y);
            unsigned long long bp1 = pk2(bq.z, bq.w);
            float ar[4]={a.x,a.y,a.z,a.w};
            #pragma unroll
            for (int i=0;i<4;i++) {
                unsigned long long ad = pk2(ar[i], ar[i]);
                acc2[i][0] = fma2(ad, bp0, acc2[i][0]);
                acc2[i][1] = fma2(ad, bp1, acc2[i][1]);
            }
        }
        __syncthreads();
    }
    float u[4][4];
    #pragma unroll
    for (int i=0;i<4;i++) {
        float2 u0 = upk2(acc2[i][0]);
        float2 u1 = upk2(acc2[i][1]);
        u[i][0]=u0.x; u[i][1]=u0.y; u[i][2]=u1.x; u[i][3]=u1.y;
    }
    #pragma unroll
    for (int j=0;j<4;j++) {
        float4 tv = make_float4(u[0][j],u[1][j],u[2][j],u[3][j]);
        *(float4*)&d_AT[((size_t)b*NP + n0 + tx*4 + j)*TWO_O + o0 + ty*4] = tv;
    }
}

// ---- gather + reduce: mx/sum/sq over 20 neighbors using A table ----
template<int O>
__global__ void k_gather() {
    constexpr int P = 16;
    constexpr int NPG = 256 / O;
    __shared__ int s_ix[P*KNN];
    int tid = threadIdx.x;
    int bn0 = blockIdx.x * P;
    for (int e = tid; e < P*KNN; e += 256) s_ix[e] = d_idx[bn0*KNN + e];
    __syncthreads();
    int pg = tid / O;
    int ol = tid - pg*O;
    float accS = 0.f, accQ = 0.f;
    for (int p = pg; p < P; p += NPG) {
        int bn = bn0 + p;
        int b = bn >> 11;
        size_t jbase = (size_t)b * NP;
        const int* ix = s_ix + p*KNN;
        float m = -3.4e38f, s = 0.f, q = 0.f;
        #pragma unroll
        for (int k=0;k<KNN;k++) {
            float v = d_AT[(jbase + ix[k])*(size_t)(2*O) + ol];
            m = fmaxf(m, v);
            s += v;
            q = fmaf(v, v, q);
        }
        float t = d_AT[(size_t)bn*(2*O) + O + ol];
        d_mx[(size_t)bn*O + ol] = m + t;
        accS += s + 20.f*t;
        accQ += q + 2.f*t*s + 20.f*t*t;
    }
    atomicAdd(&d_sum[ol], accS);
    atomicAdd(&d_sq [ol], accQ);
}

// ---- BN stats -> affine scale/shift per channel ----
__global__ void k_finalize(const float* __restrict__ g, const float* __restrict__ bb,
                           float inv, int O) {
    int o = blockIdx.x*blockDim.x + threadIdx.x;
    if (o >= O) return;
    float mean = d_sum[o]*inv;
    float var  = d_sq[o]*inv - mean*mean;
    float sc = g[o] / sqrtf(var + 1e-5f);
    d_scale[o] = sc;
    d_shift[o] = bb[o] - mean*sc;
}

// ---- apply BN+leaky to max_k and transpose into d_cat slice ----
__global__ void k_apply(int O, int coff) {
    int b = blockIdx.z;
    int n0 = blockIdx.x*32, o0 = blockIdx.y*32;
    __shared__ float tile[32][33];
    #pragma unroll
    for (int q=0;q<4;q++) {
        int n = n0 + threadIdx.y + q*8;
        int o = o0 + threadIdx.x;
        float v = d_mx[((size_t)b*NP + n)*O + o];
        float z = v*d_scale[o] + d_shift[o];
        z = (z > 0.f) ? z : 0.2f*z;
        tile[threadIdx.x][threadIdx.y + q*8] = z;
    }
    __syncthreads();
    #pragma unroll
    for (int q=0;q<4;q++) {
        int o = o0 + threadIdx.y + q*8;
        int n = n0 + threadIdx.x;
        d_cat[((size_t)b*512 + coff + o)*NP + n] = tile[threadIdx.y + q*8][threadIdx.x];
    }
}

// ---- final 512->1024 conv with channel stats (FFMA2) ----
__global__ void k_fgemm(const float* __restrict__ W5) {
    int b = blockIdx.z;
    int o0 = blockIdx.y*64, n0 = blockIdx.x*64;
    __shared__ __align__(16) float As[16][64];
    __shared__ __align__(16) float Bs[16][64];
    const float* catb = d_cat + (size_t)b*512*NP;
    int tid = threadIdx.x;
    int tx = tid & 15, ty = tid >> 4;
    int a_oi = tid >> 2;
    int a_k4 = (tid & 3) * 4;
    int b_kk = tid >> 4;
    int b_n4 = (tid & 15) * 4;
    unsigned long long acc2[4][2] = {};
    for (int c0=0;c0<512;c0+=16) {
        float4 w = *(const float4*)&W5[(size_t)(o0 + a_oi)*512 + c0 + a_k4];
        As[a_k4+0][a_oi]=w.x; As[a_k4+1][a_oi]=w.y; As[a_k4+2][a_oi]=w.z; As[a_k4+3][a_oi]=w.w;
        *(float4*)&Bs[b_kk][b_n4] = *(const float4*)&catb[(size_t)(c0 + b_kk)*NP + n0 + b_n4];
        __syncthreads();
        #pragma unroll
        for (int kk=0;kk<16;kk++) {
            float4 a  = *(float4*)&As[kk][ty*4];
            float4 bq = *(float4*)&Bs[kk][tx*4];
            unsigned long long bp0 = pk2(bq.x, bq.y);
            unsigned long long bp1 = pk2(bq.z, bq.w);
            float ar[4]={a.x,a.y,a.z,a.w};
            #pragma unroll
            for (int i=0;i<4;i++) {
                unsigned long long ad = pk2(ar[i], ar[i]);
                acc2[i][0] = fma2(ad, bp0, acc2[i][0]);
                acc2[i][1] = fma2(ad, bp1, acc2[i][1]);
            }
        }
        __syncthreads();
    }
    float s[4]={0.f,0.f,0.f,0.f}, sq[4]={0.f,0.f,0.f,0.f};
    #pragma unroll
    for (int i=0;i<4;i++) {
        int o = o0 + ty*4 + i;
        float2 u0 = upk2(acc2[i][0]);
        float2 u1 = upk2(acc2[i][1]);
        float vj[4] = {u0.x, u0.y, u1.x, u1.y};
        *(float4*)&d_Y[((size_t)b*1024 + o)*NP + n0 + tx*4] =
            make_float4(vj[0],vj[1],vj[2],vj[3]);
        #pragma unroll
        for (int j=0;j<4;j++) { s[i] += vj[j]; sq[i] += vj[j]*vj[j]; }
    }
    #pragma unroll
    for (int i=0;i<4;i++) {
        #pragma unroll
        for (int off=8;off;off>>=1) {
            s[i]  += __shfl_down_sync(0xffffffffu, s[i],  off, 16);
            sq[i] += __shfl_down_sync(0xffffffffu, sq[i], off, 16);
        }
    }
    if (tx == 0) {
        #pragma unroll
        for (int i=0;i<4;i++) {
            atomicAdd(&d_sum[o0+ty*4+i], s[i]);
            atomicAdd(&d_sq [o0+ty*4+i], sq[i]);
        }
    }
}

// ---- per (b,o): BN+leaky then max and mean over n ----
__global__ void k_freduce(float* __restrict__ out) {
    int bo = blockIdx.x;
    int b = bo >> 10, o = bo & 1023;
    const float* y = d_Y + (size_t)bo*NP;
    float sc = d_scale[o], sh = d_shift[o];
    int tid = threadIdx.x;
    float mx = -1e30f, s = 0.f;
    #pragma unroll
    for (int q=0;q<8;q++) {
        float z = y[tid + q*256]*sc + sh;
        z = (z > 0.f) ? z : 0.2f*z;
        mx = fmaxf(mx, z); s += z;
    }
    #pragma unroll
    for (int off=16;off;off>>=1) {
        mx = fmaxf(mx, __shfl_down_sync(0xffffffffu, mx, off));
        s += __shfl_down_sync(0xffffffffu, s, off);
    }
    __shared__ float smx[8], ssm[8];
    if ((tid&31)==0) { smx[tid>>5]=mx; ssm[tid>>5]=s; }
    __syncthreads();
    if (tid==0) {
        #pragma unroll
        for (int i=1;i<8;i++){ mx=fmaxf(mx,smx[i]); s+=ssm[i]; }
        out[(size_t)b*2048 + o] = mx;
        out[(size_t)b*2048 + 1024 + o] = s * (1.f/2048.f);
    }
}

// ------------------------------- host -------------------------------
template<int C, int O>
static void run_edge3(int coff_in, const float* W, const float* g, const float* bb,
                      int coff_out) {
    dim3 tb(32,8);
    k_norms<<<dim3(NP/256, B_), 256>>>(nullptr, coff_in, 0, C);
    k_gram<<<dim3(NP/64, NP/64, B_), 256>>>(nullptr, coff_in, 0, C);
    k_select<<<B_*NP, 256>>>();
    k_zero<<<4,256>>>();
    k_wprep<<<(2*O*C + 255)/256, 256>>>(W, O, C);
    k_atgemm<C, 2*O><<<dim3(NP/64, 2*O/64, B_), 256>>>(nullptr, coff_in, 0);
    k_gather<O><<<B_*NP/16, 256>>>();
    k_finalize<<<(O+127)/128,128>>>(g, bb, 1.f/(float)(B_*NP*KNN), O);
    k_apply<<<dim3(NP/32, O/32, B_), tb>>>(O, coff_out);
}

extern "C" void kernel_launch(void* const* d_in, const int* in_sizes, int n_in,
                              void* d_out, int out_size) {
    (void)in_sizes; (void)n_in; (void)out_size;
    const float* x  = (const float*)d_in[0];
    const float* W1 = (const float*)d_in[1];
    const float* W2 = (const float*)d_in[2];
    const float* W3 = (const float*)d_in[3];
    const float* W4 = (const float*)d_in[4];
    const float* W5 = (const float*)d_in[5];
    const float* g1 = (const float*)d_in[6];  const float* b1 = (const float*)d_in[7];
    const float* g2 = (const float*)d_in[8];  const float* b2 = (const float*)d_in[9];
    const float* g3 = (const float*)d_in[10]; const float* b3 = (const float*)d_in[11];
    const float* g4 = (const float*)d_in[12]; const float* b4 = (const float*)d_in[13];
    const float* g5 = (const float*)d_in[14]; const float* b5 = (const float*)d_in[15];
    float* out = (float*)d_out;

    // ---- layer 1 (C=3): legacy tiny path ----
    {
        dim3 tb(32,8);
        k_transpose<<<dim3(NP/32, 1, B_), tb>>>(x, 0, 3*NP, 3);
        k_norms<<<dim3(NP/256, B_), 256>>>(x, 0, 3*NP, 3);
        k_gram<<<dim3(NP/64, NP/64, B_), 256>>>(x, 0, 3*NP, 3);
        k_select<<<B_*NP, 256>>>();
        k_zero<<<4,256>>>();
        k_edgeconv<3,64><<<B_*NP, 64>>>(W1);
        k_finalize<<<1,128>>>(g1, b1, 1.f/(float)(B_*NP*KNN), 64);
        k_apply<<<dim3(NP/32, 2, B_), tb>>>(64, 0);
    }
    run_edge3<64,  64 >(0,   W2, g2, b2,  64);
    run_edge3<64,  128>(64,  W3, g3, b3, 128);
    run_edge3<128, 256>(128, W4, g4, b4, 256);

    k_zero<<<4,256>>>();
    k_fgemm<<<dim3(NP/64, 1024/64, B_), 256>>>(W5);
    k_finalize<<<8,128>>>(g5, b5, 1.f/(float)(B_*NP), 1024);
    k_freduce<<<B_*1024, 256>>>(out);
}

// round 5
// speedup vs baseline: 5.7183x; 1.0386x over previous
#include <cuda_runtime.h>
#include <math.h>
#include <stdint.h>

#define NP  2048
#define B_  8
#define KNN 20

// ------------------- device scratch (allocation-free) -------------------
__device__ float d_xx[B_*NP];
__device__ float d_D[(size_t)B_*NP*NP];                       // 134 MB distances
__device__ int   d_idx[B_*NP*KNN];
__device__ __align__(16) float d_xT[(size_t)B_*NP*4];         // layer-1 gather layout
__device__ __align__(16) float d_cat[(size_t)B_*512*NP];      // x1..x4 stacked [B,512,N]
__device__ __align__(16) float d_mx[(size_t)B_*NP*256];       // pre-BN max over k
__device__ __align__(16) float d_AT[(size_t)B_*NP*512];       // [bn][2O]: A then T
__device__ __align__(16) float d_WG[512*128];                 // [Wn; Wd] rows
__device__ __align__(16) float d_Y[(size_t)B_*1024*NP];       // final conv out
__device__ float d_sum[1024];
__device__ float d_sq[1024];
__device__ float d_scale[1024];
__device__ float d_shift[1024];

// ---- packed f32x2 helpers (FFMA2 path) ----
__device__ __forceinline__ unsigned long long pk2(float lo, float hi) {
    unsigned long long r;
    asm("mov.b64 %0, {%1, %2};" : "=l"(r) : "f"(lo), "f"(hi));
    return r;
}
__device__ __forceinline__ float2 upk2(unsigned long long v) {
    float lo, hi;
    asm("mov.b64 {%0, %1}, %2;" : "=f"(lo), "=f"(hi) : "l"(v));
    return make_float2(lo, hi);
}
__device__ __forceinline__ unsigned long long fma2(unsigned long long a,
                                                   unsigned long long b,
                                                   unsigned long long c) {
    unsigned long long d;
    asm("fma.rn.f32x2 %0, %1, %2, %3;" : "=l"(d) : "l"(a), "l"(b), "l"(c));
    return d;
}

__device__ __forceinline__ const float* layer_src(const float* ext, int coff, int b, int bstride) {
    if (ext) return ext + (size_t)b * bstride;
    return d_cat + (size_t)b * 512 * NP + (size_t)coff * NP;
}

// ---- 8x8 FFMA2 microkernel step over a 16-deep smem tile ----
__device__ __forceinline__ void mk_step(const float* As, const float* Bs,
                                        int aoff, int boff,
                                        unsigned long long (&acc)[8][4]) {
    #pragma unroll
    for (int kk=0; kk<16; kk++) {
        const float* ar = As + kk*128 + aoff;
        const float* br = Bs + kk*128 + boff;
        float4 a0 = *(const float4*)ar;
        float4 a1 = *(const float4*)(ar+4);
        float4 b0 = *(const float4*)br;
        float4 b1 = *(const float4*)(br+4);
        unsigned long long bp[4] = {pk2(b0.x,b0.y), pk2(b0.z,b0.w),
                                    pk2(b1.x,b1.y), pk2(b1.z,b1.w)};
        float av[8] = {a0.x,a0.y,a0.z,a0.w,a1.x,a1.y,a1.z,a1.w};
        #pragma unroll
        for (int i=0;i<8;i++) {
            unsigned long long ad = pk2(av[i], av[i]);
            #pragma unroll
            for (int jp=0;jp<4;jp++) acc[i][jp] = fma2(ad, bp[jp], acc[i][jp]);
        }
    }
}

// ---- transpose src slice [C,NP] -> d_xT [NP,C] (layer 1 only) ----
__global__ void k_transpose(const float* ext, int coff, int bstride, int C) {
    int b = blockIdx.z;
    const float* S = layer_src(ext, coff, b, bstride);
    __shared__ float tile[32][33];
    int n0 = blockIdx.x*32, c0 = blockIdx.y*32;
    #pragma unroll
    for (int q=0;q<4;q++) {
        int c = c0 + threadIdx.y + q*8;
        if (c < C) tile[threadIdx.y + q*8][threadIdx.x] = S[(size_t)c*NP + n0 + threadIdx.x];
    }
    __syncthreads();
    #pragma unroll
    for (int q=0;q<4;q++) {
        int n = n0 + threadIdx.y + q*8;
        int c = c0 + threadIdx.x;
        if (c < C) d_xT[((size_t)b*NP + n)*C + c] = tile[threadIdx.x][threadIdx.y + q*8];
    }
}

// ---- squared norms per point ----
__global__ void k_norms(const float* ext, int coff, int bstride, int C) {
    int b = blockIdx.y;
    int n = blockIdx.x*256 + threadIdx.x;
    const float* S = layer_src(ext, coff, b, bstride);
    float s = 0.f;
    for (int c=0;c<C;c++){ float v = S[(size_t)c*NP + n]; s += v*v; }
    d_xx[b*NP + n] = s;
}

// ---- layer-1 gram (C=3, old 64x64 path) ----
__global__ void k_gram(const float* ext, int coff, int bstride, int C) {
    int b = blockIdx.z;
    const float* S = layer_src(ext, coff, b, bstride);
    int n0 = blockIdx.y*64, m0 = blockIdx.x*64;
    __shared__ __align__(16) float As[16][64];
    __shared__ __align__(16) float Bs[16][64];
    int tid = threadIdx.x;
    int tx = tid & 15, ty = tid >> 4;
    int lr = tid >> 4;
    int lc = (tid & 15) * 4;
    unsigned long long acc2[4][2] = {};
    for (int c0=0;c0<C;c0+=16) {
        float4 av, bv;
        if (c0 + lr < C) {
            av = *(const float4*)&S[(size_t)(c0+lr)*NP + n0 + lc];
            bv = *(const float4*)&S[(size_t)(c0+lr)*NP + m0 + lc];
        } else { av = make_float4(0.f,0.f,0.f,0.f); bv = av; }
        *(float4*)&As[lr][lc] = av;
        *(float4*)&Bs[lr][lc] = bv;
        __syncthreads();
        #pragma unroll
        for (int kk=0;kk<16;kk++) {
            float4 a  = *(float4*)&As[kk][ty*4];
            float4 bq = *(float4*)&Bs[kk][tx*4];
            unsigned long long bp0 = pk2(bq.x, bq.y);
            unsigned long long bp1 = pk2(bq.z, bq.w);
            float ar[4] = {a.x,a.y,a.z,a.w};
            #pragma unroll
            for (int i=0;i<4;i++) {
                unsigned long long ad = pk2(ar[i], ar[i]);
                acc2[i][0] = fma2(ad, bp0, acc2[i][0]);
                acc2[i][1] = fma2(ad, bp1, acc2[i][1]);
            }
        }
        __syncthreads();
    }
    float xn[4], xm[4];
    #pragma unroll
    for (int i=0;i<4;i++) xn[i] = d_xx[b*NP + n0 + ty*4 + i];
    #pragma unroll
    for (int j=0;j<4;j++) xm[j] = d_xx[b*NP + m0 + tx*4 + j];
    #pragma unroll
    for (int i=0;i<4;i++) {
        float2 u0 = upk2(acc2[i][0]);
        float2 u1 = upk2(acc2[i][1]);
        float4 w;
        w.x = 2.f*u0.x - xn[i] - xm[0];
        w.y = 2.f*u0.y - xn[i] - xm[1];
        w.z = 2.f*u1.x - xn[i] - xm[2];
        w.w = 2.f*u1.y - xn[i] - xm[3];
        *(float4*)&d_D[((size_t)b*NP + n0+ty*4+i)*NP + m0+tx*4] = w;
    }
}

// ---- gram 128x128 / 8x8 FFMA2 (layers 2-4, C multiple of 16) ----
template<int C>
__global__ __launch_bounds__(256) void k_gram2(int coff) {
    int b = blockIdx.z;
    const float* S = d_cat + (size_t)b*512*NP + (size_t)coff*NP;
    int n0 = blockIdx.y*128, m0 = blockIdx.x*128;
    __shared__ __align__(16) float As[16*128];
    __shared__ __align__(16) float Bs[16*128];
    int tid = threadIdx.x;
    int lrow = tid >> 4, lcol = (tid & 15) * 8;
    int lane = tid & 31, w = tid >> 5;
    int aoff = (w & 3)*32 + (lane >> 3)*8;
    int boff = (w >> 2)*64 + (lane & 7)*8;
    unsigned long long acc[8][4] = {};
    for (int c0=0;c0<C;c0+=16) {
        const float* Sr = S + (size_t)(c0+lrow)*NP;
        *(float4*)&As[lrow*128+lcol]   = *(const float4*)&Sr[n0+lcol];
        *(float4*)&As[lrow*128+lcol+4] = *(const float4*)&Sr[n0+lcol+4];
        *(float4*)&Bs[lrow*128+lcol]   = *(const float4*)&Sr[m0+lcol];
        *(float4*)&Bs[lrow*128+lcol+4] = *(const float4*)&Sr[m0+lcol+4];
        __syncthreads();
        mk_step(As, Bs, aoff, boff, acc);
        __syncthreads();
    }
    float xm[8];
    #pragma unroll
    for (int j=0;j<8;j++) xm[j] = d_xx[b*NP + m0 + boff + j];
    #pragma unroll
    for (int i=0;i<8;i++) {
        float xn = d_xx[b*NP + n0 + aoff + i];
        float2 u0 = upk2(acc[i][0]);
        float2 u1 = upk2(acc[i][1]);
        float2 u2 = upk2(acc[i][2]);
        float2 u3 = upk2(acc[i][3]);
        float4 w0, w1;
        w0.x = 2.f*u0.x - xn - xm[0];
        w0.y = 2.f*u0.y - xn - xm[1];
        w0.z = 2.f*u1.x - xn - xm[2];
        w0.w = 2.f*u1.y - xn - xm[3];
        w1.x = 2.f*u2.x - xn - xm[4];
        w1.y = 2.f*u2.y - xn - xm[5];
        w1.z = 2.f*u3.x - xn - xm[6];
        w1.w = 2.f*u3.y - xn - xm[7];
        float* dst = &d_D[((size_t)b*NP + n0 + aoff + i)*NP + m0 + boff];
        *(float4*)dst = w0;
        *(float4*)(dst+4) = w1;
    }
}

// ---- top-20 SET per row via 8-bit radix histogram select (order-free) ----
__global__ void k_select() {
    int bn = blockIdx.x;
    __shared__ unsigned int key[NP];
    __shared__ unsigned int hist[256];
    __shared__ unsigned int sh_v, sh_need2, sh_cnt;
    const float* row = d_D + (size_t)bn*NP;
    int tid = threadIdx.x;  // 256
    #pragma unroll
    for (int q=0;q<8;q++) {
        int m = tid + q*256;
        unsigned int fb = __float_as_uint(row[m]);
        key[m] = (fb & 0x80000000u) ? ~fb : (fb | 0x80000000u);
    }
    unsigned prefix = 0, pmask = 0, need = KNN;
    int done = 0;
    for (int shift = 24; shift >= 0; shift -= 8) {
        hist[tid] = 0;
        __syncthreads();
        #pragma unroll
        for (int q=0;q<8;q++) {
            unsigned k = key[tid + q*256];
            if ((k & pmask) == prefix) atomicAdd(&hist[(k >> shift) & 255u], 1u);
        }
        __syncthreads();
        if (tid < 32) {
            unsigned base = tid*8;
            unsigned suf[8]; unsigned s = 0;
            #pragma unroll
            for (int j=7;j>=0;j--){ s += hist[base+j]; suf[j] = s; }
            unsigned incl = s;
            #pragma unroll
            for (int d=1; d<32; d<<=1) {
                unsigned o = __shfl_down_sync(0xffffffffu, incl, d);
                if (tid + d < 32) incl += o;
            }
            unsigned lane_above = incl - s;
            #pragma unroll
            for (int j=0;j<8;j++) {
                unsigned cg  = lane_above + suf[j];
                unsigned cgt = cg - hist[base+j];
                if (cgt < need && need <= cg) { sh_v = base + j; sh_need2 = need - cgt; }
            }
        }
        __syncthreads();
        unsigned v = sh_v, n2 = sh_need2, binc = hist[v];
        prefix |= v << shift;
        pmask  |= 0xffu << shift;
        need = n2;
        if (n2 == binc) { done = 1; break; }
        __syncthreads();
    }
    if (tid == 0) sh_cnt = 0;
    __syncthreads();
    #pragma unroll
    for (int q=0;q<8;q++) {
        int m = tid + q*256;
        unsigned k = key[m];
        bool take = done ? (k >= prefix) : (k > prefix);
        if (take) { unsigned slot = atomicAdd(&sh_cnt, 1u); d_idx[bn*KNN + slot] = m; }
    }
    __syncthreads();
    if (!done) {
        #pragma unroll
        for (int q=0;q<8;q++) {
            int m = tid + q*256;
            if (key[m] == prefix) {
                unsigned slot = atomicAdd(&sh_cnt, 1u);
                if (slot < KNN) d_idx[bn*KNN + slot] = m;
            }
        }
    }
}

__global__ void k_zero() {
    int i = blockIdx.x*blockDim.x + threadIdx.x;
    if (i < 1024) { d_sum[i]=0.f; d_sq[i]=0.f; }
}

// ---- legacy edge conv for layer 1 (C=3 — tiny) ----
template<int C, int O>
__global__ void k_edgeconv(const float* __restrict__ W) {
    int bn = blockIdx.x;
    int b = bn >> 11;
    int n = bn & (NP-1);
    constexpr int CP = (C < 4) ? 4 : C;
    __shared__ __align__(16) float s_ctr[CP];
    __shared__ __align__(16) float s_nbr[KNN*CP];
    __shared__ int s_idx[KNN];
    int tid = threadIdx.x;
    int TH = blockDim.x;
    if (tid < KNN) s_idx[tid] = d_idx[bn*KNN + tid];
    const float* xb = d_xT + (size_t)b*NP*C;
    for (int c=tid;c<C;c+=TH) s_ctr[c] = xb[(size_t)n*C + c];
    __syncthreads();
    for (int e=tid;e<KNN*C;e+=TH) {
        int j = e / C, c = e - j*C;
        s_nbr[j*CP + c] = xb[(size_t)s_idx[j]*C + c];
    }
    __syncthreads();
    for (int o=tid;o<O;o+=TH) {
        const float* Wo = W + o*2*C;
        float t = 0.f;
        for (int c=0;c<C;c++) t += (Wo[C+c] - Wo[c]) * s_ctr[c];
        float y[KNN];
        #pragma unroll
        for (int k=0;k<KNN;k++) y[k] = t;
        for (int c=0;c<C;c++) {
            float w = Wo[c];
            #pragma unroll
            for (int k=0;k<KNN;k++) y[k] += w * s_nbr[k*CP + c];
        }
        float mx = -1e30f, s = 0.f, sq = 0.f;
        #pragma unroll
        for (int k=0;k<KNN;k++) {
            mx = fmaxf(mx, y[k]);
            s += y[k];
            sq += y[k]*y[k];
        }
        d_mx[(size_t)bn*O + o] = mx;
        atomicAdd(&d_sum[o], s);
        atomicAdd(&d_sq[o], sq);
    }
}

// ---- build combined weights: rows [0,O) = Wn, rows [O,2O) = W2 - Wn ----
__global__ void k_wprep(const float* __restrict__ W, int O, int C) {
    int i = blockIdx.x*256 + threadIdx.x;
    if (i >= 2*O*C) return;
    int o = i / C, c = i - o*C;
    if (o < O) d_WG[i] = W[(size_t)o*2*C + c];
    else {
        int oo = o - O;
        d_WG[i] = W[(size_t)oo*2*C + C + c] - W[(size_t)oo*2*C + c];
    }
}

// ---- AT GEMM 128x128 / 8x8: d_AT[bn][o] = sum_c WG[o][c]*src[c][n] ----
template<int C, int TWO_O>
__global__ __launch_bounds__(256) void k_atgemm2(int coff) {
    int b = blockIdx.z;
    int o0 = blockIdx.y*128, n0 = blockIdx.x*128;
    const float* src = d_cat + (size_t)b*512*NP + (size_t)coff*NP;
    __shared__ __align__(16) float As[16*128];
    __shared__ __align__(16) float Bs[16*128];
    int tid = threadIdx.x;
    int lrow = tid >> 4, lcol = (tid & 15) * 8;
    int o_l = tid >> 1, kh = (tid & 1) * 8;
    int lane = tid & 31, w = tid >> 5;
    int aoff = (w & 3)*32 + (lane >> 3)*8;
    int boff = (w >> 2)*64 + (lane & 7)*8;
    unsigned long long acc[8][4] = {};
    for (int c0=0;c0<C;c0+=16) {
        float4 w0 = *(const float4*)&d_WG[(size_t)(o0+o_l)*C + c0 + kh];
        float4 w1 = *(const float4*)&d_WG[(size_t)(o0+o_l)*C + c0 + kh + 4];
        As[(kh+0)*128+o_l]=w0.x; As[(kh+1)*128+o_l]=w0.y;
        As[(kh+2)*128+o_l]=w0.z; As[(kh+3)*128+o_l]=w0.w;
        As[(kh+4)*128+o_l]=w1.x; As[(kh+5)*128+o_l]=w1.y;
        As[(kh+6)*128+o_l]=w1.z; As[(kh+7)*128+o_l]=w1.w;
        const float* Sr = src + (size_t)(c0+lrow)*NP;
        *(float4*)&Bs[lrow*128+lcol]   = *(const float4*)&Sr[n0+lcol];
        *(float4*)&Bs[lrow*128+lcol+4] = *(const float4*)&Sr[n0+lcol+4];
        __syncthreads();
        mk_step(As, Bs, aoff, boff, acc);
        __syncthreads();
    }
    float u[8][8];
    #pragma unroll
    for (int i=0;i<8;i++) {
        #pragma unroll
        for (int jp=0;jp<4;jp++) {
            float2 p = upk2(acc[i][jp]);
            u[i][jp*2] = p.x; u[i][jp*2+1] = p.y;
        }
    }
    #pragma unroll
    for (int j=0;j<8;j++) {
        float* dst = &d_AT[((size_t)b*NP + n0 + boff + j)*TWO_O + o0 + aoff];
        *(float4*)dst     = make_float4(u[0][j],u[1][j],u[2][j],u[3][j]);
        *(float4*)(dst+4) = make_float4(u[4][j],u[5][j],u[6][j],u[7][j]);
    }
}

// ---- gather + reduce: mx/sum/sq over 20 neighbors using A table ----
template<int O>
__global__ void k_gather() {
    constexpr int P = 16;
    constexpr int NPG = 256 / O;
    __shared__ int s_ix[P*KNN];
    int tid = threadIdx.x;
    int bn0 = blockIdx.x * P;
    for (int e = tid; e < P*KNN; e += 256) s_ix[e] = d_idx[bn0*KNN + e];
    __syncthreads();
    int pg = tid / O;
    int ol = tid - pg*O;
    float accS = 0.f, accQ = 0.f;
    for (int p = pg; p < P; p += NPG) {
        int bn = bn0 + p;
        int b = bn >> 11;
        size_t jbase = (size_t)b * NP;
        const int* ix = s_ix + p*KNN;
        float m = -3.4e38f, s = 0.f, q = 0.f;
        #pragma unroll
        for (int k=0;k<KNN;k++) {
            float v = d_AT[(jbase + ix[k])*(size_t)(2*O) + ol];
            m = fmaxf(m, v);
            s += v;
            q = fmaf(v, v, q);
        }
        float t = d_AT[(size_t)bn*(2*O) + O + ol];
        d_mx[(size_t)bn*O + ol] = m + t;
        accS += s + 20.f*t;
        accQ += q + 2.f*t*s + 20.f*t*t;
    }
    atomicAdd(&d_sum[ol], accS);
    atomicAdd(&d_sq [ol], accQ);
}

// ---- BN stats -> affine scale/shift per channel ----
__global__ void k_finalize(const float* __restrict__ g, const float* __restrict__ bb,
                           float inv, int O) {
    int o = blockIdx.x*blockDim.x + threadIdx.x;
    if (o >= O) return;
    float mean = d_sum[o]*inv;
    float var  = d_sq[o]*inv - mean*mean;
    float sc = g[o] / sqrtf(var + 1e-5f);
    d_scale[o] = sc;
    d_shift[o] = bb[o] - mean*sc;
}

// ---- apply BN+leaky to max_k and transpose into d_cat slice ----
__global__ void k_apply(int O, int coff) {
    int b = blockIdx.z;
    int n0 = blockIdx.x*32, o0 = blockIdx.y*32;
    __shared__ float tile[32][33];
    #pragma unroll
    for (int q=0;q<4;q++) {
        int n = n0 + threadIdx.y + q*8;
        int o = o0 + threadIdx.x;
        float v = d_mx[((size_t)b*NP + n)*O + o];
        float z = v*d_scale[o] + d_shift[o];
        z = (z > 0.f) ? z : 0.2f*z;
        tile[threadIdx.x][threadIdx.y + q*8] = z;
    }
    __syncthreads();
    #pragma unroll
    for (int q=0;q<4;q++) {
        int o = o0 + threadIdx.y + q*8;
        int n = n0 + threadIdx.x;
        d_cat[((size_t)b*512 + coff + o)*NP + n] = tile[threadIdx.y + q*8][threadIdx.x];
    }
}

// ---- final 512->1024 conv 128x128 / 8x8 with channel stats ----
__global__ __launch_bounds__(256) void k_fgemm2(const float* __restrict__ W5) {
    int b = blockIdx.z;
    int o0 = blockIdx.y*128, n0 = blockIdx.x*128;
    const float* catb = d_cat + (size_t)b*512*NP;
    __shared__ __align__(16) float As[16*128];
    __shared__ __align__(16) float Bs[16*128];
    int tid = threadIdx.x;
    int lrow = tid >> 4, lcol = (tid & 15) * 8;
    int o_l = tid >> 1, kh = (tid & 1) * 8;
    int lane = tid & 31, w = tid >> 5;
    int aoff = (w & 3)*32 + (lane >> 3)*8;
    int boff = (w >> 2)*64 + (lane & 7)*8;
    int ln = lane & 7;
    unsigned long long acc[8][4] = {};
    for (int c0=0;c0<512;c0+=16) {
        float4 w0 = *(const float4*)&W5[(size_t)(o0+o_l)*512 + c0 + kh];
        float4 w1 = *(const float4*)&W5[(size_t)(o0+o_l)*512 + c0 + kh + 4];
        As[(kh+0)*128+o_l]=w0.x; As[(kh+1)*128+o_l]=w0.y;
        As[(kh+2)*128+o_l]=w0.z; As[(kh+3)*128+o_l]=w0.w;
        As[(kh+4)*128+o_l]=w1.x; As[(kh+5)*128+o_l]=w1.y;
        As[(kh+6)*128+o_l]=w1.z; As[(kh+7)*128+o_l]=w1.w;
        const float* Sr = catb + (size_t)(c0+lrow)*NP;
        *(float4*)&Bs[lrow*128+lcol]   = *(const float4*)&Sr[n0+lcol];
        *(float4*)&Bs[lrow*128+lcol+4] = *(const float4*)&Sr[n0+lcol+4];
        __syncthreads();
        mk_step(As, Bs, aoff, boff, acc);
        __syncthreads();
    }
    float s8[8], q8[8];
    #pragma unroll
    for (int i=0;i<8;i++) {
        float2 u0 = upk2(acc[i][0]);
        float2 u1 = upk2(acc[i][1]);
        float2 u2 = upk2(acc[i][2]);
        float2 u3 = upk2(acc[i][3]);
        float vj[8] = {u0.x,u0.y,u1.x,u1.y,u2.x,u2.y,u3.x,u3.y};
        float* dst = &d_Y[((size_t)b*1024 + o0 + aoff + i)*NP + n0 + boff];
        *(float4*)dst     = make_float4(vj[0],vj[1],vj[2],vj[3]);
        *(float4*)(dst+4) = make_float4(vj[4],vj[5],vj[6],vj[7]);
        float s = 0.f, q = 0.f;
        #pragma unroll
        for (int j=0;j<8;j++) { s += vj[j]; q = fmaf(vj[j], vj[j], q); }
        s8[i] = s; q8[i] = q;
    }
    #pragma unroll
    for (int i=0;i<8;i++) {
        #pragma unroll
        for (int off=4;off;off>>=1) {
            s8[i] += __shfl_down_sync(0xffffffffu, s8[i], off, 8);
            q8[i] += __shfl_down_sync(0xffffffffu, q8[i], off, 8);
        }
    }
    if (ln == 0) {
        #pragma unroll
        for (int i=0;i<8;i++) {
            atomicAdd(&d_sum[o0 + aoff + i], s8[i]);
            atomicAdd(&d_sq [o0 + aoff + i], q8[i]);
        }
    }
}

// ---- per (b,o): BN+leaky then max and mean over n ----
__global__ void k_freduce(float* __restrict__ out) {
    int bo = blockIdx.x;
    int b = bo >> 10, o = bo & 1023;
    const float* y = d_Y + (size_t)bo*NP;
    float sc = d_scale[o], sh = d_shift[o];
    int tid = threadIdx.x;
    float mx = -1e30f, s = 0.f;
    #pragma unroll
    for (int q=0;q<8;q++) {
        float z = y[tid + q*256]*sc + sh;
        z = (z > 0.f) ? z : 0.2f*z;
        mx = fmaxf(mx, z); s += z;
    }
    #pragma unroll
    for (int off=16;off;off>>=1) {
        mx = fmaxf(mx, __shfl_down_sync(0xffffffffu, mx, off));
        s += __shfl_down_sync(0xffffffffu, s, off);
    }
    __shared__ float smx[8], ssm[8];
    if ((tid&31)==0) { smx[tid>>5]=mx; ssm[tid>>5]=s; }
    __syncthreads();
    if (tid==0) {
        #pragma unroll
        for (int i=1;i<8;i++){ mx=fmaxf(mx,smx[i]); s+=ssm[i]; }
        out[(size_t)b*2048 + o] = mx;
        out[(size_t)b*2048 + 1024 + o] = s * (1.f/2048.f);
    }
}

// ------------------------------- host -------------------------------
template<int C, int O>
static void run_edge4(int coff_in, const float* W, const float* g, const float* bb,
                      int coff_out) {
    dim3 tb(32,8);
    k_norms<<<dim3(NP/256, B_), 256>>>(nullptr, coff_in, 0, C);
    k_gram2<C><<<dim3(NP/128, NP/128, B_), 256>>>(coff_in);
    k_select<<<B_*NP, 256>>>();
    k_zero<<<4,256>>>();
    k_wprep<<<(2*O*C + 255)/256, 256>>>(W, O, C);
    k_atgemm2<C, 2*O><<<dim3(NP/128, 2*O/128, B_), 256>>>(coff_in);
    k_gather<O><<<B_*NP/16, 256>>>();
    k_finalize<<<(O+127)/128,128>>>(g, bb, 1.f/(float)(B_*NP*KNN), O);
    k_apply<<<dim3(NP/32, O/32, B_), tb>>>(O, coff_out);
}

extern "C" void kernel_launch(void* const* d_in, const int* in_sizes, int n_in,
                              void* d_out, int out_size) {
    (void)in_sizes; (void)n_in; (void)out_size;
    const float* x  = (const float*)d_in[0];
    const float* W1 = (const float*)d_in[1];
    const float* W2 = (const float*)d_in[2];
    const float* W3 = (const float*)d_in[3];
    const float* W4 = (const float*)d_in[4];
    const float* W5 = (const float*)d_in[5];
    const float* g1 = (const float*)d_in[6];  const float* b1 = (const float*)d_in[7];
    const float* g2 = (const float*)d_in[8];  const float* b2 = (const float*)d_in[9];
    const float* g3 = (const float*)d_in[10]; const float* b3 = (const float*)d_in[11];
    const float* g4 = (const float*)d_in[12]; const float* b4 = (const float*)d_in[13];
    const float* g5 = (const float*)d_in[14]; const float* b5 = (const float*)d_in[15];
    float* out = (float*)d_out;

    // ---- layer 1 (C=3): legacy tiny path ----
    {
        dim3 tb(32,8);
        k_transpose<<<dim3(NP/32, 1, B_), tb>>>(x, 0, 3*NP, 3);
        k_norms<<<dim3(NP/256, B_), 256>>>(x, 0, 3*NP, 3);
        k_gram<<<dim3(NP/64, NP/64, B_), 256>>>(x, 0, 3*NP, 3);
        k_select<<<B_*NP, 256>>>();
        k_zero<<<4,256>>>();
        k_edgeconv<3,64><<<B_*NP, 64>>>(W1);
        k_finalize<<<1,128>>>(g1, b1, 1.f/(float)(B_*NP*KNN), 64);
        k_apply<<<dim3(NP/32, 2, B_), tb>>>(64, 0);
    }
    run_edge4<64,  64 >(0,   W2, g2, b2,  64);
    run_edge4<64,  128>(64,  W3, g3, b3, 128);
    run_edge4<128, 256>(128, W4, g4, b4, 256);

    k_zero<<<4,256>>>();
    k_fgemm2<<<dim3(NP/128, 1024/128, B_), 256>>>(W5);
    k_finalize<<<8,128>>>(g5, b5, 1.f/(float)(B_*NP), 1024);
    k_freduce<<<B_*1024, 256>>>(out);
}